// round 7
// baseline (speedup 1.0000x reference)
#include <cuda_runtime.h>
#include <cuda_fp16.h>
#include <math.h>
#include <stdint.h>

#define T_CTX 100000
#define H 256

// ---- GEMM tiling: warp mma f16 m16n8k16, warp tile 64x64, CTA 128x256 ----
#define TILE_M 128                               // rows per CTA
#define NB_G ((T_CTX + TILE_M - 1) / TILE_M)     // 782
#define KT 64                                    // K chunk (elements)
#define NCH (H / KT)                             // 4
#define ASTR 72                                  // fp16 row stride: conflict-free
#define ABUF_H (TILE_M * ASTR)                   // 9216 halves / chunk buffer
#define BBUF_H (H * ASTR)                        // 18432 halves / buffer
// 4 A chunk buffers (persistent) + 2 B buffers + red(512f) + at_s(128f)
#define SMEM_GEMM ((4 * ABUF_H + 2 * BBUF_H) * 2 + (4 * TILE_M + TILE_M) * 4) // 150016

// ---- softmax / ct reduce ----
#define SM_BLOCKS 98
#define CTR1 64

// Scratch (static device globals: allocation-free per harness rules)
__device__ float g_At[T_CTX];
__device__ float g_proj[H];
__device__ __half g_WmTh[H * H];                 // Wm transposed, fp16(rn)
__device__ float g_lse;
__device__ float g_sm_m[SM_BLOCKS];
__device__ float g_sm_s[SM_BLOCKS];
__device__ float g_ct1[NB_G][H];                 // per-CTA  Σ At[t]·M[t,h]
__device__ float g_cs1[NB_G][H];                 // per-CTA  Σ M[t,h]
__device__ float g_ct2[CTR1][H];
__device__ float g_cs2[CTR1][H];

// ===========================================================================
// helpers
// ===========================================================================
__device__ __forceinline__ float tanh_fast(float x) {
    float y;
    asm("tanh.approx.f32 %0, %1;" : "=f"(y) : "f"(x));
    return y;
}
__device__ __forceinline__ uint32_t smem_u32(const void* p) {
    uint32_t a;
    asm("{ .reg .u64 t; cvta.to.shared.u64 t, %1; cvt.u32.u64 %0, t; }" : "=r"(a) : "l"(p));
    return a;
}
__device__ __forceinline__ void cp16(uint32_t dst, const void* src) {
    asm volatile("cp.async.cg.shared.global [%0], [%1], 16;" :: "r"(dst), "l"(src) : "memory");
}
__device__ __forceinline__ void cp_commit() {
    asm volatile("cp.async.commit_group;" ::: "memory");
}
__device__ __forceinline__ void ldsm4(uint32_t& r0, uint32_t& r1, uint32_t& r2, uint32_t& r3,
                                      uint32_t addr) {
    asm volatile("ldmatrix.sync.aligned.m8n8.x4.shared.b16 {%0,%1,%2,%3}, [%4];"
                 : "=r"(r0), "=r"(r1), "=r"(r2), "=r"(r3) : "r"(addr));
}
__device__ __forceinline__ void mma_f16(float d[4], const uint32_t a[4], const uint32_t b[2]) {
    asm volatile(
        "mma.sync.aligned.m16n8k16.row.col.f32.f16.f16.f32 "
        "{%0,%1,%2,%3}, {%4,%5,%6,%7}, {%8,%9}, {%0,%1,%2,%3};"
        : "+f"(d[0]), "+f"(d[1]), "+f"(d[2]), "+f"(d[3])
        : "r"(a[0]), "r"(a[1]), "r"(a[2]), "r"(a[3]), "r"(b[0]), "r"(b[1]));
}

// ===========================================================================
// proj = hc @ W1^T  (tiny)
// ===========================================================================
__global__ void proj_kernel(const float* __restrict__ hc, const float* __restrict__ W1) {
    int j = threadIdx.x;
    float s = 0.f;
#pragma unroll 8
    for (int k = 0; k < H; ++k) s = fmaf(hc[k], W1[j * H + k], s);
    g_proj[j] = s;
}

// ===========================================================================
// WmTh[n][k] = f16(Wm[k][n])
// ===========================================================================
__global__ void transpose_kernel(const float* __restrict__ Wm) {
    __shared__ float t[32][33];
    int bx = blockIdx.x & 7, by = blockIdx.x >> 3;
    int x = bx * 32 + threadIdx.x;
#pragma unroll
    for (int j = 0; j < 4; ++j) {
        int y = by * 32 + threadIdx.y + j * 8;
        t[threadIdx.y + j * 8][threadIdx.x] = Wm[y * H + x];
    }
    __syncthreads();
    int x2 = by * 32 + threadIdx.x;
#pragma unroll
    for (int j = 0; j < 4; ++j) {
        int y2 = bx * 32 + threadIdx.y + j * 8;
        g_WmTh[y2 * H + x2] = __float2half_rn(t[threadIdx.x][threadIdx.y + j * 8]);
    }
}

// ===========================================================================
// Fused GEMM + tanh + V-dot + ct partials.
// CTA 128x256xK256, 8 warps (2 row x 4 col groups), warp tile 64x64.
// A: LDG f32 -> cvt f16 in regs -> STS into 4 persistent chunk buffers.
// B: cp.async double-buffered. Fragments via ldmatrix.x4.
// ===========================================================================
__global__ void __launch_bounds__(256, 1)
gemm_tanh_mma(const float* __restrict__ A,      // inputs T x H (f32)
              const float* __restrict__ V) {    // H
    extern __shared__ __half smh[];
    __half* As = smh;                            // [4][TILE_M][ASTR]
    __half* Bs = smh + 4 * ABUF_H;               // [2][H][ASTR]
    float* red = (float*)(smh + 4 * ABUF_H + 2 * BBUF_H);  // [4][TILE_M]
    float* at_s = red + 4 * TILE_M;              // [TILE_M]
    const uint32_t as_u = smem_u32(As);
    const uint32_t bs_u = smem_u32(Bs);

    const int tid = threadIdx.x;
    const int wid = tid >> 5;
    const int lane = tid & 31;
    const int g = lane >> 2;
    const int t = lane & 3;
    const int rg = wid >> 2;          // row group (0..1): rows rg*64..
    const int wc = wid & 3;           // col group (0..3): cols wc*64..
    const int row0 = blockIdx.x * TILE_M;

    // ldmatrix lane-address bases (bytes), chunk 0 / buffer 0
    uint32_t a_lm[4], b_lm[4];
#pragma unroll
    for (int mt = 0; mt < 4; ++mt)
        a_lm[mt] = as_u + 2u * ((uint32_t)(rg * 64 + mt * 16 + (lane & 7) +
                                ((lane >> 3) & 1) * 8) * ASTR + ((lane >> 4) & 1) * 8);
#pragma unroll
    for (int np = 0; np < 4; ++np)
        b_lm[np] = bs_u + 2u * ((uint32_t)(wc * 64 + np * 16 + (lane & 7) +
                                ((lane >> 4) & 1) * 8) * ASTR + ((lane >> 3) & 1) * 8);

    uint32_t ph[16];                  // prefetched A chunk as half2 (16 regs)
    float acc[4][8][4];
#pragma unroll
    for (int mt = 0; mt < 4; ++mt)
#pragma unroll
        for (int nt = 0; nt < 8; ++nt)
#pragma unroll
            for (int r = 0; r < 4; ++r) acc[mt][nt][r] = 0.f;

    auto ldgA = [&](int ch) {
        const int k0 = ch * KT;
#pragma unroll
        for (int i = 0; i < 8; ++i) {
            int idx = tid + i * 256;
            int r = idx >> 4;                 // 16 float4 per row (64 f32)
            int c = (idx & 15) * 4;
            int grow = row0 + r;
            float4 v = (grow < T_CTX)
                ? *reinterpret_cast<const float4*>(&A[(size_t)grow * H + k0 + c])
                : make_float4(0.f, 0.f, 0.f, 0.f);
            __half2 h0 = __floats2half2_rn(v.x, v.y);
            __half2 h1 = __floats2half2_rn(v.z, v.w);
            ph[2 * i]     = *reinterpret_cast<uint32_t*>(&h0);
            ph[2 * i + 1] = *reinterpret_cast<uint32_t*>(&h1);
        }
    };
    auto stsA = [&](int buf) {
#pragma unroll
        for (int i = 0; i < 8; ++i) {
            int idx = tid + i * 256;
            int r = idx >> 4;
            int c = (idx & 15) * 4;
            *reinterpret_cast<uint2*>(&As[buf * ABUF_H + r * ASTR + c]) =
                make_uint2(ph[2 * i], ph[2 * i + 1]);
        }
    };
    auto cpB = [&](int ch, int buf) {
        const int k0 = ch * KT;
#pragma unroll
        for (int i = 0; i < 8; ++i) {
            int idx = tid + i * 256;
            int n = idx >> 3;                 // 8 x 16B per row of 64 halves
            int c8 = (idx & 7) * 8;
            cp16(bs_u + (uint32_t)(buf * BBUF_H + n * ASTR + c8) * 2,
                 g_WmTh + (size_t)n * H + k0 + c8);
        }
        cp_commit();
    };

    auto compute = [&](int ch, int bbuf) {
        const uint32_t aoff = (uint32_t)ch * (ABUF_H * 2);
        const uint32_t boff = (uint32_t)bbuf * (BBUF_H * 2);
#pragma unroll
        for (int ks = 0; ks < 4; ++ks) {
            const uint32_t koff = ks * 32;       // 16 halves
            uint32_t bf[8][2];
#pragma unroll
            for (int np = 0; np < 4; ++np)
                ldsm4(bf[2 * np][0], bf[2 * np][1], bf[2 * np + 1][0], bf[2 * np + 1][1],
                      b_lm[np] + boff + koff);
#pragma unroll
            for (int mt = 0; mt < 4; ++mt) {
                uint32_t af[4];
                ldsm4(af[0], af[1], af[2], af[3], a_lm[mt] + aoff + koff);
#pragma unroll
                for (int nt = 0; nt < 8; ++nt)
                    mma_f16(acc[mt][nt], af, bf[nt]);
            }
        }
    };

    // ---- prologue ----
    ldgA(0); cpB(0, 0);
    stsA(0);
    ldgA(1); cpB(1, 1);
    asm volatile("cp.async.wait_group 1;" ::: "memory");   // B0 arrived
    __syncthreads();

    // ---- mainloop: 4 chunks; A buffer = ch, B buffer = ch&1 ----
#pragma unroll
    for (int ch = 0; ch < NCH; ++ch) {
        const int bbuf = ch & 1;
        if (ch < NCH - 1) stsA(ch + 1);
        if (ch < NCH - 2) ldgA(ch + 2);
        compute(ch, bbuf);
        if (ch < NCH - 1) {
            __syncthreads();                   // done reading B(bbuf); A(ch+1) visible
            if (ch < NCH - 2) {
                cpB(ch + 2, bbuf);
                asm volatile("cp.async.wait_group 1;" ::: "memory");
            } else {
                asm volatile("cp.async.wait_group 0;" ::: "memory");
            }
            __syncthreads();
        }
    }

    // --- epilogue 1: tanh + V-dot ---
    float p[8] = {0.f, 0.f, 0.f, 0.f, 0.f, 0.f, 0.f, 0.f};
#pragma unroll
    for (int nt = 0; nt < 8; ++nt) {
        int cn = wc * 64 + nt * 8 + t * 2;
        float v0 = V[cn],      v1 = V[cn + 1];
        float q0 = g_proj[cn], q1 = g_proj[cn + 1];
#pragma unroll
        for (int mt = 0; mt < 4; ++mt) {
            p[mt * 2 + 0] = fmaf(tanh_fast(acc[mt][nt][0] + q0), v0,
                            fmaf(tanh_fast(acc[mt][nt][1] + q1), v1, p[mt * 2 + 0]));
            p[mt * 2 + 1] = fmaf(tanh_fast(acc[mt][nt][2] + q0), v0,
                            fmaf(tanh_fast(acc[mt][nt][3] + q1), v1, p[mt * 2 + 1]));
        }
    }
#pragma unroll
    for (int j = 0; j < 8; ++j) {
        p[j] += __shfl_xor_sync(0xffffffffu, p[j], 1);
        p[j] += __shfl_xor_sync(0xffffffffu, p[j], 2);
    }
    if (t == 0) {
#pragma unroll
        for (int mt = 0; mt < 4; ++mt)
#pragma unroll
            for (int h = 0; h < 2; ++h)
                red[wc * TILE_M + rg * 64 + mt * 16 + h * 8 + g] = p[mt * 2 + h];
    }
    __syncthreads();
    if (tid < TILE_M) {
        float s = ((red[tid] + red[TILE_M + tid]) +
                   (red[2 * TILE_M + tid] + red[3 * TILE_M + tid]));
        at_s[tid] = s;
        int grow = row0 + tid;
        if (grow < T_CTX) g_At[grow] = s;
    }
    __syncthreads();

    // --- epilogue 2: ct partials from resident fp16 A tiles ---
    // thread = column c; OOB rows were written as 0 so they contribute nothing.
    {
        const int c = tid;
        const __half* col = As + (c >> 6) * ABUF_H + (c & 63);
        float s1 = 0.f, s2 = 0.f;
#pragma unroll 8
        for (int r = 0; r < TILE_M; ++r) {
            float f = __half2float(col[r * ASTR]);
            s1 = fmaf(at_s[r], f, s1);
            s2 += f;
        }
        g_ct1[blockIdx.x][c] = s1;
        g_cs1[blockIdx.x][c] = s2;
    }
}

// ===========================================================================
// Two-stage logsumexp over At
// ===========================================================================
__global__ void softmax_part_kernel() {
    __shared__ float wred[32];
    const int tid = threadIdx.x;
    const int lane = tid & 31;
    const int wid = tid >> 5;
    const int tt = blockIdx.x * 1024 + tid;

    float v = (tt < T_CTX) ? g_At[tt] : -1e30f;
    float m = v;
#pragma unroll
    for (int s = 16; s > 0; s >>= 1) m = fmaxf(m, __shfl_xor_sync(~0u, m, s));
    if (lane == 0) wred[wid] = m;
    __syncthreads();
    if (wid == 0) {
        float mm = wred[lane];
#pragma unroll
        for (int s = 16; s > 0; s >>= 1) mm = fmaxf(mm, __shfl_xor_sync(~0u, mm, s));
        wred[lane] = mm;
    }
    __syncthreads();
    const float bm = wred[0];

    float sum = expf(v - bm);
#pragma unroll
    for (int s = 16; s > 0; s >>= 1) sum += __shfl_xor_sync(~0u, sum, s);
    __syncthreads();
    if (lane == 0) wred[wid] = sum;
    __syncthreads();
    if (tid == 0) {
        float S = 0.f;
#pragma unroll
        for (int i = 0; i < 32; ++i) S += wred[i];   // fixed order
        g_sm_m[blockIdx.x] = bm;
        g_sm_s[blockIdx.x] = S;
    }
}

__global__ void softmax_final_kernel() {
    const int lane = threadIdx.x;        // 32
    float m = -1e30f;
    for (int i = lane; i < SM_BLOCKS; i += 32) m = fmaxf(m, g_sm_m[i]);
#pragma unroll
    for (int s = 16; s > 0; s >>= 1) m = fmaxf(m, __shfl_xor_sync(~0u, m, s));
    float S = 0.f;
    for (int i = lane; i < SM_BLOCKS; i += 32) S += g_sm_s[i] * expf(g_sm_m[i] - m);
#pragma unroll
    for (int s = 16; s > 0; s >>= 1) S += __shfl_xor_sync(~0u, S, s);
    if (lane == 0) g_lse = m + logf(S);
}

// ===========================================================================
// alphat = At - lse
// ===========================================================================
__global__ void alpha_kernel(float* __restrict__ out_alpha) {
    int t = blockIdx.x * 1024 + threadIdx.x;
    if (t < T_CTX) out_alpha[t] = g_At[t] - g_lse;
}

// ===========================================================================
// ct reduction: ct[c] = Σ ct1 − lse · Σ cs1   (fixed-order, deterministic)
// ===========================================================================
__global__ void __launch_bounds__(256)
ctred1_kernel() {
    const int j = blockIdx.x;            // 0..CTR1-1
    const int c = threadIdx.x;           // 256
    float s1a = 0.f, s1b = 0.f, s2a = 0.f, s2b = 0.f;
    int b = j;
    for (; b + CTR1 < NB_G; b += 2 * CTR1) {     // 2-way MLP, fixed order per slot
        s1a += g_ct1[b][c];         s2a += g_cs1[b][c];
        s1b += g_ct1[b + CTR1][c];  s2b += g_cs1[b + CTR1][c];
    }
    for (; b < NB_G; b += CTR1) { s1a += g_ct1[b][c]; s2a += g_cs1[b][c]; }
    g_ct2[j][c] = s1a + s1b;
    g_cs2[j][c] = s2a + s2b;
}

__global__ void ctred2_kernel(float* __restrict__ out_ct) {
    const int c = threadIdx.x;
    float s1 = 0.f, s2 = 0.f;
#pragma unroll
    for (int j = 0; j < CTR1; ++j) {             // fixed order
        s1 += g_ct2[j][c];
        s2 += g_cs2[j][c];
    }
    out_ct[c] = s1 - g_lse * s2;
}

// ===========================================================================
extern "C" void kernel_launch(void* const* d_in, const int* in_sizes, int n_in,
                              void* d_out, int out_size) {
    const float* inputs = (const float*)d_in[0];   // (T, H)
    const float* hc     = (const float*)d_in[1];   // (1, H)
    const float* Wm     = (const float*)d_in[2];   // (H, H)
    const float* V      = (const float*)d_in[3];   // (H, 1)
    const float* W1     = (const float*)d_in[4];   // (H, H)
    float* out = (float*)d_out;                    // [alphat (T) | ct (H)]

    static int smem_set = 0;
    if (!smem_set) {
        cudaFuncSetAttribute(gemm_tanh_mma,
                             cudaFuncAttributeMaxDynamicSharedMemorySize, SMEM_GEMM);
        smem_set = 1;
    }

    proj_kernel<<<1, 256>>>(hc, W1);
    transpose_kernel<<<64, dim3(32, 8)>>>(Wm);
    gemm_tanh_mma<<<NB_G, 256, SMEM_GEMM>>>(inputs, V);
    ctred1_kernel<<<CTR1, 256>>>();                 // lse-independent
    softmax_part_kernel<<<SM_BLOCKS, 1024>>>();
    softmax_final_kernel<<<1, 32>>>();
    alpha_kernel<<<(T_CTX + 1023) / 1024, 1024>>>(out);
    ctred2_kernel<<<1, 256>>>(out + T_CTX);
}

// round 8
// speedup vs baseline: 1.1045x; 1.1045x over previous
#include <cuda_runtime.h>
#include <cuda_fp16.h>
#include <math.h>
#include <stdint.h>

#define T_CTX 100000
#define H 256

// ---- GEMM tiling (round-6 config: warp tile 32x64, CTA 64x256, 2 CTA/SM) ----
#define TILE_M 64                                // rows per CTA
#define NB_G ((T_CTX + TILE_M - 1) / TILE_M)     // 1563
#define KT 64                                    // K chunk (elements)
#define NCH (H / KT)                             // 4
#define ASTR 72                                  // fp16 row stride: conflict-free
#define ABUF_H (TILE_M * ASTR)                   // 4608 halves / chunk buffer
#define BBUF_H (H * ASTR)                        // 18432 halves / buffer
#define SMEM_GEMM ((4 * ABUF_H + 2 * BBUF_H) * 2 + (4 * TILE_M + TILE_M) * 4) // 111872

// ---- softmax / ct reduce ----
#define SM_BLOCKS 98
#define CTRB 32                                  // ctred1 blocks -> 128 partial rows
#define CTR_ROWS (CTRB * 4)                      // 128

// Scratch (static device globals: allocation-free per harness rules)
__device__ float g_At[T_CTX];
__device__ float g_proj[H];
__device__ __half g_WmTh[H * H];                 // Wm transposed, fp16(rn)
__device__ float g_lse;
__device__ float g_sm_m[SM_BLOCKS];
__device__ float g_sm_s[SM_BLOCKS];
__device__ float g_ct1[NB_G][H];                 // per-CTA  Σ At[t]·M[t,h]
__device__ float g_cs1[NB_G][H];                 // per-CTA  Σ M[t,h]
__device__ float g_ct2[CTR_ROWS][H];
__device__ float g_cs2[CTR_ROWS][H];

// ===========================================================================
// helpers
// ===========================================================================
__device__ __forceinline__ float tanh_fast(float x) {
    float y;
    asm("tanh.approx.f32 %0, %1;" : "=f"(y) : "f"(x));
    return y;
}
__device__ __forceinline__ uint32_t smem_u32(const void* p) {
    uint32_t a;
    asm("{ .reg .u64 t; cvta.to.shared.u64 t, %1; cvt.u32.u64 %0, t; }" : "=r"(a) : "l"(p));
    return a;
}
__device__ __forceinline__ void cp16(uint32_t dst, const void* src) {
    asm volatile("cp.async.cg.shared.global [%0], [%1], 16;" :: "r"(dst), "l"(src) : "memory");
}
__device__ __forceinline__ void cp_commit() {
    asm volatile("cp.async.commit_group;" ::: "memory");
}
__device__ __forceinline__ void ldsm4(uint32_t& r0, uint32_t& r1, uint32_t& r2, uint32_t& r3,
                                      uint32_t addr) {
    asm volatile("ldmatrix.sync.aligned.m8n8.x4.shared.b16 {%0,%1,%2,%3}, [%4];"
                 : "=r"(r0), "=r"(r1), "=r"(r2), "=r"(r3) : "r"(addr));
}
__device__ __forceinline__ void mma_f16(float d[4], const uint32_t a[4], const uint32_t b[2]) {
    asm volatile(
        "mma.sync.aligned.m16n8k16.row.col.f32.f16.f16.f32 "
        "{%0,%1,%2,%3}, {%4,%5,%6,%7}, {%8,%9}, {%0,%1,%2,%3};"
        : "+f"(d[0]), "+f"(d[1]), "+f"(d[2]), "+f"(d[3])
        : "r"(a[0]), "r"(a[1]), "r"(a[2]), "r"(a[3]), "r"(b[0]), "r"(b[1]));
}

// ===========================================================================
// proj = hc @ W1^T  (tiny)
// ===========================================================================
__global__ void proj_kernel(const float* __restrict__ hc, const float* __restrict__ W1) {
    int j = threadIdx.x;
    float s = 0.f;
#pragma unroll 8
    for (int k = 0; k < H; ++k) s = fmaf(hc[k], W1[j * H + k], s);
    g_proj[j] = s;
}

// ===========================================================================
// WmTh[n][k] = f16(Wm[k][n])
// ===========================================================================
__global__ void transpose_kernel(const float* __restrict__ Wm) {
    __shared__ float t[32][33];
    int bx = blockIdx.x & 7, by = blockIdx.x >> 3;
    int x = bx * 32 + threadIdx.x;
#pragma unroll
    for (int j = 0; j < 4; ++j) {
        int y = by * 32 + threadIdx.y + j * 8;
        t[threadIdx.y + j * 8][threadIdx.x] = Wm[y * H + x];
    }
    __syncthreads();
    int x2 = by * 32 + threadIdx.x;
#pragma unroll
    for (int j = 0; j < 4; ++j) {
        int y2 = bx * 32 + threadIdx.y + j * 8;
        g_WmTh[y2 * H + x2] = __float2half_rn(t[threadIdx.x][threadIdx.y + j * 8]);
    }
}

// ===========================================================================
// Fused GEMM + tanh + V-dot + ct partials (round-6 proven config).
// CTA 64x256xK256, 8 warps (2 row x 4 col groups), warp tile 32x64.
// ===========================================================================
__global__ void __launch_bounds__(256, 2)
gemm_tanh_mma(const float* __restrict__ A,      // inputs T x H (f32)
              const float* __restrict__ V) {    // H
    extern __shared__ __half smh[];
    __half* As = smh;                            // [4][TILE_M][ASTR]
    __half* Bs = smh + 4 * ABUF_H;               // [2][H][ASTR]
    float* red = (float*)(smh + 4 * ABUF_H + 2 * BBUF_H);  // [4][TILE_M]
    float* at_s = red + 4 * TILE_M;              // [TILE_M]
    const uint32_t as_u = smem_u32(As);
    const uint32_t bs_u = smem_u32(Bs);

    const int tid = threadIdx.x;
    const int wid = tid >> 5;
    const int lane = tid & 31;
    const int g = lane >> 2;
    const int t = lane & 3;
    const int rg = wid >> 2;          // row group (0..1)
    const int wc = wid & 3;           // col group (0..3)
    const int row0 = blockIdx.x * TILE_M;

    // ldmatrix lane-address bases (bytes), chunk 0 / buffer 0
    uint32_t a_lm[2], b_lm[4];
#pragma unroll
    for (int mt = 0; mt < 2; ++mt)
        a_lm[mt] = as_u + 2u * ((uint32_t)(rg * 32 + mt * 16 + (lane & 7) +
                                ((lane >> 3) & 1) * 8) * ASTR + ((lane >> 4) & 1) * 8);
#pragma unroll
    for (int np = 0; np < 4; ++np)
        b_lm[np] = bs_u + 2u * ((uint32_t)(wc * 64 + np * 16 + (lane & 7) +
                                ((lane >> 4) & 1) * 8) * ASTR + ((lane >> 3) & 1) * 8);

    float4 pa[4];
    float acc[2][8][4];
#pragma unroll
    for (int mt = 0; mt < 2; ++mt)
#pragma unroll
        for (int nt = 0; nt < 8; ++nt)
#pragma unroll
            for (int r = 0; r < 4; ++r) acc[mt][nt][r] = 0.f;

    auto ldgA = [&](int ch) {
        const int k0 = ch * KT;
#pragma unroll
        for (int i = 0; i < 4; ++i) {
            int idx = tid + i * 256;
            int r = idx >> 4;
            int c = (idx & 15) * 4;
            int grow = row0 + r;
            pa[i] = (grow < T_CTX)
                ? *reinterpret_cast<const float4*>(&A[(size_t)grow * H + k0 + c])
                : make_float4(0.f, 0.f, 0.f, 0.f);
        }
    };
    auto stsA = [&](int buf) {
#pragma unroll
        for (int i = 0; i < 4; ++i) {
            int idx = tid + i * 256;
            int r = idx >> 4;
            int c = (idx & 15) * 4;
            *reinterpret_cast<__half2*>(&As[buf * ABUF_H + r * ASTR + c]) =
                __floats2half2_rn(pa[i].x, pa[i].y);
            *reinterpret_cast<__half2*>(&As[buf * ABUF_H + r * ASTR + c + 2]) =
                __floats2half2_rn(pa[i].z, pa[i].w);
        }
    };
    auto cpB = [&](int ch, int buf) {
        const int k0 = ch * KT;
#pragma unroll
        for (int i = 0; i < 8; ++i) {
            int idx = tid + i * 256;
            int n = idx >> 3;
            int c8 = (idx & 7) * 8;
            cp16(bs_u + (uint32_t)(buf * BBUF_H + n * ASTR + c8) * 2,
                 g_WmTh + (size_t)n * H + k0 + c8);
        }
        cp_commit();
    };

    auto compute = [&](int ch, int bbuf) {
        const uint32_t aoff = (uint32_t)ch * (ABUF_H * 2);
        const uint32_t boff = (uint32_t)bbuf * (BBUF_H * 2);
#pragma unroll
        for (int ks = 0; ks < 4; ++ks) {
            const uint32_t koff = ks * 32;       // 16 halves
            uint32_t bf[8][2];
#pragma unroll
            for (int np = 0; np < 4; ++np)
                ldsm4(bf[2 * np][0], bf[2 * np][1], bf[2 * np + 1][0], bf[2 * np + 1][1],
                      b_lm[np] + boff + koff);
#pragma unroll
            for (int mt = 0; mt < 2; ++mt) {
                uint32_t af[4];
                ldsm4(af[0], af[1], af[2], af[3], a_lm[mt] + aoff + koff);
#pragma unroll
                for (int nt = 0; nt < 8; ++nt)
                    mma_f16(acc[mt][nt], af, bf[nt]);
            }
        }
    };

    // ---- prologue ----
    ldgA(0); cpB(0, 0);
    stsA(0);
    ldgA(1); cpB(1, 1);
    asm volatile("cp.async.wait_group 1;" ::: "memory");   // B0 arrived
    __syncthreads();

    // ---- mainloop: 4 chunks; A buffer = ch, B buffer = ch&1 ----
#pragma unroll
    for (int ch = 0; ch < NCH; ++ch) {
        const int bbuf = ch & 1;
        if (ch < NCH - 1) stsA(ch + 1);
        if (ch < NCH - 2) ldgA(ch + 2);
        compute(ch, bbuf);
        if (ch < NCH - 1) {
            __syncthreads();                   // done reading B(bbuf); A(ch+1) visible
            if (ch < NCH - 2) {
                cpB(ch + 2, bbuf);
                asm volatile("cp.async.wait_group 1;" ::: "memory");
            } else {
                asm volatile("cp.async.wait_group 0;" ::: "memory");
            }
            __syncthreads();
        }
    }

    // --- epilogue 1: tanh + V-dot ---
    float p[4] = {0.f, 0.f, 0.f, 0.f};
#pragma unroll
    for (int nt = 0; nt < 8; ++nt) {
        int cn = wc * 64 + nt * 8 + t * 2;
        float v0 = V[cn],      v1 = V[cn + 1];
        float q0 = g_proj[cn], q1 = g_proj[cn + 1];
#pragma unroll
        for (int mt = 0; mt < 2; ++mt) {
            p[mt * 2 + 0] = fmaf(tanh_fast(acc[mt][nt][0] + q0), v0,
                            fmaf(tanh_fast(acc[mt][nt][1] + q1), v1, p[mt * 2 + 0]));
            p[mt * 2 + 1] = fmaf(tanh_fast(acc[mt][nt][2] + q0), v0,
                            fmaf(tanh_fast(acc[mt][nt][3] + q1), v1, p[mt * 2 + 1]));
        }
    }
#pragma unroll
    for (int j = 0; j < 4; ++j) {
        p[j] += __shfl_xor_sync(0xffffffffu, p[j], 1);
        p[j] += __shfl_xor_sync(0xffffffffu, p[j], 2);
    }
    if (t == 0) {
#pragma unroll
        for (int mt = 0; mt < 2; ++mt)
#pragma unroll
            for (int h = 0; h < 2; ++h)
                red[wc * TILE_M + rg * 32 + mt * 16 + h * 8 + g] = p[mt * 2 + h];
    }
    __syncthreads();
    if (tid < TILE_M) {
        float s = ((red[tid] + red[TILE_M + tid]) +
                   (red[2 * TILE_M + tid] + red[3 * TILE_M + tid]));
        at_s[tid] = s;
        int grow = row0 + tid;
        if (grow < T_CTX) g_At[grow] = s;
    }
    __syncthreads();

    // --- epilogue 2: ct partials from resident fp16 A tiles ---
    {
        const int c = tid;
        const __half* col = As + (c >> 6) * ABUF_H + (c & 63);
        float s1 = 0.f, s2 = 0.f;
#pragma unroll 8
        for (int r = 0; r < TILE_M; ++r) {
            float f = __half2float(col[r * ASTR]);
            s1 = fmaf(at_s[r], f, s1);
            s2 += f;
        }
        g_ct1[blockIdx.x][c] = s1;
        g_cs1[blockIdx.x][c] = s2;
    }
}

// ===========================================================================
// Two-stage logsumexp over At
// ===========================================================================
__global__ void softmax_part_kernel() {
    __shared__ float wred[32];
    const int tid = threadIdx.x;
    const int lane = tid & 31;
    const int wid = tid >> 5;
    const int tt = blockIdx.x * 1024 + tid;

    float v = (tt < T_CTX) ? g_At[tt] : -1e30f;
    float m = v;
#pragma unroll
    for (int s = 16; s > 0; s >>= 1) m = fmaxf(m, __shfl_xor_sync(~0u, m, s));
    if (lane == 0) wred[wid] = m;
    __syncthreads();
    if (wid == 0) {
        float mm = wred[lane];
#pragma unroll
        for (int s = 16; s > 0; s >>= 1) mm = fmaxf(mm, __shfl_xor_sync(~0u, mm, s));
        wred[lane] = mm;
    }
    __syncthreads();
    const float bm = wred[0];

    float sum = expf(v - bm);
#pragma unroll
    for (int s = 16; s > 0; s >>= 1) sum += __shfl_xor_sync(~0u, sum, s);
    __syncthreads();
    if (lane == 0) wred[wid] = sum;
    __syncthreads();
    if (tid == 0) {
        float S = 0.f;
#pragma unroll
        for (int i = 0; i < 32; ++i) S += wred[i];   // fixed order
        g_sm_m[blockIdx.x] = bm;
        g_sm_s[blockIdx.x] = S;
    }
}

__global__ void softmax_final_kernel() {
    const int lane = threadIdx.x;        // 32
    float m = -1e30f;
    for (int i = lane; i < SM_BLOCKS; i += 32) m = fmaxf(m, g_sm_m[i]);
#pragma unroll
    for (int s = 16; s > 0; s >>= 1) m = fmaxf(m, __shfl_xor_sync(~0u, m, s));
    float S = 0.f;
    for (int i = lane; i < SM_BLOCKS; i += 32) S += g_sm_s[i] * expf(g_sm_m[i] - m);
#pragma unroll
    for (int s = 16; s > 0; s >>= 1) S += __shfl_xor_sync(~0u, S, s);
    if (lane == 0) g_lse = m + logf(S);
}

// ===========================================================================
// alphat = At - lse
// ===========================================================================
__global__ void alpha_kernel(float* __restrict__ out_alpha) {
    int t = blockIdx.x * 1024 + threadIdx.x;
    if (t < T_CTX) out_alpha[t] = g_At[t] - g_lse;
}

// ===========================================================================
// ct reduction stage 1: 32 blocks x (4 row-lanes x 64 float4-cols).
// Coalesced float4 loads, 2 independent streams, fixed order per slot.
// ===========================================================================
__global__ void __launch_bounds__(256)
ctred1_kernel() {
    const int tid = threadIdx.x;
    const int rl = tid >> 6;             // 0..3
    const int fc = (tid & 63) * 4;       // float col
    const int row = blockIdx.x * 4 + rl; // 0..127

    float4 s1 = make_float4(0.f, 0.f, 0.f, 0.f);
    float4 s2 = make_float4(0.f, 0.f, 0.f, 0.f);
    for (int b = row; b < NB_G; b += CTR_ROWS) {
        float4 v1 = *reinterpret_cast<const float4*>(&g_ct1[b][fc]);
        float4 v2 = *reinterpret_cast<const float4*>(&g_cs1[b][fc]);
        s1.x += v1.x; s1.y += v1.y; s1.z += v1.z; s1.w += v1.w;
        s2.x += v2.x; s2.y += v2.y; s2.z += v2.z; s2.w += v2.w;
    }
    *reinterpret_cast<float4*>(&g_ct2[row][fc]) = s1;
    *reinterpret_cast<float4*>(&g_cs2[row][fc]) = s2;
}

// ===========================================================================
// ct reduction stage 2: 1024 threads = 4 row-slices x 256 cols + smem combine
// ===========================================================================
__global__ void __launch_bounds__(1024)
ctred2_kernel(float* __restrict__ out_ct) {
    __shared__ float sm1[4][H];
    __shared__ float sm2[4][H];
    const int c = threadIdx.x & 255;
    const int js = threadIdx.x >> 8;     // 0..3, rows js*32 .. js*32+31
    float s1 = 0.f, s2 = 0.f;
#pragma unroll 8
    for (int j = js * 32; j < js * 32 + 32; ++j) {   // fixed order
        s1 += g_ct2[j][c];
        s2 += g_cs2[j][c];
    }
    sm1[js][c] = s1;
    sm2[js][c] = s2;
    __syncthreads();
    if (js == 0) {
        float t1 = ((sm1[0][c] + sm1[1][c]) + (sm1[2][c] + sm1[3][c]));
        float t2 = ((sm2[0][c] + sm2[1][c]) + (sm2[2][c] + sm2[3][c]));
        out_ct[c] = t1 - g_lse * t2;
    }
}

// ===========================================================================
extern "C" void kernel_launch(void* const* d_in, const int* in_sizes, int n_in,
                              void* d_out, int out_size) {
    const float* inputs = (const float*)d_in[0];   // (T, H)
    const float* hc     = (const float*)d_in[1];   // (1, H)
    const float* Wm     = (const float*)d_in[2];   // (H, H)
    const float* V      = (const float*)d_in[3];   // (H, 1)
    const float* W1     = (const float*)d_in[4];   // (H, H)
    float* out = (float*)d_out;                    // [alphat (T) | ct (H)]

    static int smem_set = 0;
    if (!smem_set) {
        cudaFuncSetAttribute(gemm_tanh_mma,
                             cudaFuncAttributeMaxDynamicSharedMemorySize, SMEM_GEMM);
        smem_set = 1;
    }

    proj_kernel<<<1, 256>>>(hc, W1);
    transpose_kernel<<<64, dim3(32, 8)>>>(Wm);
    gemm_tanh_mma<<<NB_G, 256, SMEM_GEMM>>>(inputs, V);
    ctred1_kernel<<<CTRB, 256>>>();                 // lse-independent
    softmax_part_kernel<<<SM_BLOCKS, 1024>>>();
    softmax_final_kernel<<<1, 32>>>();
    alpha_kernel<<<(T_CTX + 1023) / 1024, 1024>>>(out);
    ctred2_kernel<<<1, 1024>>>(out + T_CTX);
}